// round 10
// baseline (speedup 1.0000x reference)
#include <cuda_runtime.h>
#include <cstdint>
#include <cstddef>

#define BB 2
#define LL 2048
#define HH 16
#define EE 64
#define BS 256
#define NB (LL / BS)                  // 8 blocks
#define OUT_ELEMS (BB * LL * HH * EE) // output tensor precedes attn in d_out

// smem layout (floats)
#define QT_OFF 0                      // Q^T: 64 e x 128 rows (quad-swizzled)      8192 f
#define KS_OFF 8192                   // K^T-dup chunk, later aliased by S chunk   8192 f
#define SV_OFF 16384                  // V-dup chunk: 64 keys x 64 cols dup'd      8192 f
#define SMEMF  24576                  // 98304 bytes -> 2 CTAs/SM

typedef unsigned long long ull;

__device__ __forceinline__ ull pack2(float lo, float hi) {
    ull r;
    asm("mov.b64 %0, {%1, %2};" : "=l"(r) : "f"(lo), "f"(hi));
    return r;
}
__device__ __forceinline__ void unpack2(ull p, float &lo, float &hi) {
    asm("mov.b64 {%0, %1}, %2;" : "=f"(lo), "=f"(hi) : "l"(p));
}
__device__ __forceinline__ void fma2(ull &d, ull a, ull b) {
    asm("fma.rn.f32x2 %0, %1, %2, %0;" : "+l"(d) : "l"(a), "l"(b));
}

extern __shared__ float sm[];

__global__ void __launch_bounds__(256, 2)
sparse_attn_kernel(const float *__restrict__ Q,
                   const float *__restrict__ K,
                   const float *__restrict__ V,
                   float *__restrict__ out) {
    const int tid = threadIdx.x;
    const int bid = blockIdx.x;
    const int hf  = bid & 1;          // which 128-row half of the block
    const int blk = (bid >> 1) & 7;
    const int h   = (bid >> 4) & 15;
    const int b   = bid >> 8;

    const int kg = tid & 15;   // key/col group (4 wide)
    const int rg = tid >> 4;   // row group: rows rg*8 .. rg*8+7 (local, 0..127)

    const float *Qrow = Q + ((size_t)(b * LL + blk * BS + hf * 128) * HH + h) * EE;
    const float *Krow = K + ((size_t)(b * LL + blk * BS) * HH + h) * EE;
    const float *Vrow = V + ((size_t)(b * LL + blk * BS) * HH + h) * EE;

    float *attnBase = out + (size_t)OUT_ELEMS + (size_t)(b * HH + h) * LL * LL +
                      (size_t)(blk * BS + hf * 128) * LL + (size_t)(blk * BS);
    float *attnCta  = out + (size_t)OUT_ELEMS + (size_t)(b * HH + h) * LL * LL +
                      (size_t)(blk * BS + hf * 128) * LL;
    const int blk64 = blk * 64;

    // ---- stage Q transposed with quad-swizzle: [e][quad ^ (e>>2)] ----
    #pragma unroll
    for (int i = 0; i < 8; i++) {
        int idx = i * 256 + tid;        // 2048 float4
        int r   = idx >> 4;
        int c4  = idx & 15;
        float4 f = *(const float4 *)(Qrow + r * 1024 + c4 * 4);
        const int q  = r >> 2;
        const int rl = r & 3;
        sm[QT_OFF + (c4 * 4 + 0) * 128 + ((q ^ c4) << 2) + rl] = f.x;
        sm[QT_OFF + (c4 * 4 + 1) * 128 + ((q ^ c4) << 2) + rl] = f.y;
        sm[QT_OFF + (c4 * 4 + 2) * 128 + ((q ^ c4) << 2) + rl] = f.z;
        sm[QT_OFF + (c4 * 4 + 3) * 128 + ((q ^ c4) << 2) + rl] = f.w;
    }

    ull accO[16];                       // accO[cc*4+rp]
    #pragma unroll
    for (int i = 0; i < 16; i++) accO[i] = 0ULL;
    float msum[8];
    #pragma unroll
    for (int i = 0; i < 8; i++) msum[i] = 0.f;

    for (int c = 0; c < 4; c++) {
        // ---- stage K^T chunk and V chunk, both DUPLICATED {v,v} ----
        // K[key][e]  -> KS_OFF + e*128 + (key&3)*32 + (((key>>2) ^ (e&15))<<1)
        // V[key][cc] -> SV_OFF + key*128 + (cc&3)*32 + (((cc>>2) ^ (key&15))<<1)
        #pragma unroll
        for (int i = 0; i < 4; i++) {
            int idx = i * 256 + tid;    // 1024 float4 per tensor
            int key = idx >> 4;
            int c4  = idx & 15;
            float4 f = *(const float4 *)(Krow + (size_t)(c * 64 + key) * 1024 + c4 * 4);
            const int kq = key >> 2;
            const int kb32 = (key & 3) * 32;
            float fv[4] = {f.x, f.y, f.z, f.w};
            #pragma unroll
            for (int j = 0; j < 4; j++) {
                const int e = c4 * 4 + j;
                *(ull *)(sm + KS_OFF + e * 128 + kb32 + ((kq ^ (e & 15)) << 1)) =
                    pack2(fv[j], fv[j]);
            }
            float4 g = *(const float4 *)(Vrow + (size_t)(c * 64 + key) * 1024 + c4 * 4);
            float gv[4] = {g.x, g.y, g.z, g.w};
            const int kx = key & 15;
            #pragma unroll
            for (int j = 0; j < 4; j++) {
                *(ull *)(sm + SV_OFF + key * 128 + j * 32 + ((c4 ^ kx) << 1)) =
                    pack2(gv[j], gv[j]);
            }
        }
        // ---- interleaved zero-fill of this CTA's off-diag rows ----
        {
            #pragma unroll
            for (int rr = 0; rr < 2; rr++) {
                float *zp = attnCta + (size_t)(rg + 32 * c + 16 * rr) * LL;
                #pragma unroll 7
                for (int j = 0; j < 28; j++) {
                    int c4 = j * 16 + kg;
                    c4 = (c4 >= blk64) ? c4 + 64 : c4;
                    __stcs((float4 *)(zp + c4 * 4),
                           make_float4(0.f, 0.f, 0.f, 0.f));
                }
            }
        }
        __syncthreads();

        // ---- GEMM1: S = Q . K^T  (8 rows x 4 keys; K read as dup-pairs) ----
        ull acc[16];
        #pragma unroll
        for (int i = 0; i < 16; i++) acc[i] = 0ULL;
        #pragma unroll 4
        for (int x = 0; x < 16; x++) {
            const float *qa = sm + QT_OFF + x * 512 + (((2 * rg)     ^ x) << 2);
            const float *qb = sm + QT_OFF + x * 512 + (((2 * rg + 1) ^ x) << 2);
            const int m4 = (x & 3) * 4;
            #pragma unroll
            for (int ee = 0; ee < 4; ee++) {
                ulonglong2 qA = *(const ulonglong2 *)(qa + ee * 128);
                ulonglong2 qB = *(const ulonglong2 *)(qb + ee * 128);
                const float *kb = sm + KS_OFF + (x * 4 + ee) * 128 +
                                  ((kg ^ (m4 + ee)) << 1);
                ull k0 = *(const ull *)(kb);
                ull k1 = *(const ull *)(kb + 32);
                ull k2 = *(const ull *)(kb + 64);
                ull k3 = *(const ull *)(kb + 96);
                fma2(acc[0],  qA.x, k0); fma2(acc[1],  qA.y, k0);
                fma2(acc[2],  qB.x, k0); fma2(acc[3],  qB.y, k0);
                fma2(acc[4],  qA.x, k1); fma2(acc[5],  qA.y, k1);
                fma2(acc[6],  qB.x, k1); fma2(acc[7],  qB.y, k1);
                fma2(acc[8],  qA.x, k2); fma2(acc[9],  qA.y, k2);
                fma2(acc[10], qB.x, k2); fma2(acc[11], qB.y, k2);
                fma2(acc[12], qA.x, k3); fma2(acc[13], qA.y, k3);
                fma2(acc[14], qB.x, k3); fma2(acc[15], qB.y, k3);
            }
        }
        // ---- exp, row partial sums, attn STG (before barrier: hides) ----
        float ev[4][8];
        #pragma unroll
        for (int kk = 0; kk < 4; kk++)
            #pragma unroll
            for (int rp = 0; rp < 4; rp++)
                unpack2(acc[kk * 4 + rp], ev[kk][2 * rp], ev[kk][2 * rp + 1]);
        #pragma unroll
        for (int kk = 0; kk < 4; kk++)
            #pragma unroll
            for (int rr = 0; rr < 8; rr++)
                ev[kk][rr] = __expf(ev[kk][rr]);   // no-max softmax: |s| bounded
        #pragma unroll
        for (int rr = 0; rr < 8; rr++)
            msum[rr] += (ev[0][rr] + ev[1][rr]) + (ev[2][rr] + ev[3][rr]);
        {
            float *arow = attnBase + (size_t)(rg * 8) * LL + c * 64 + kg * 4;
            #pragma unroll
            for (int rr = 0; rr < 8; rr++)
                *(float4 *)(arow + (size_t)rr * LL) =
                    make_float4(ev[0][rr], ev[1][rr], ev[2][rr], ev[3][rr]);
        }
        __syncthreads();   // all GEMM1 reads of KS done -> safe to alias with S

        // ---- S -> smem (aliases the K chunk buffer) ----
        #pragma unroll
        for (int kk = 0; kk < 4; kk++) {
            const int key = kg * 4 + kk;
            float *spb = sm + KS_OFF + key * 128;
            *(float4 *)(spb + (((2 * rg)     ^ kg) << 2)) =
                make_float4(ev[kk][0], ev[kk][1], ev[kk][2], ev[kk][3]);
            *(float4 *)(spb + (((2 * rg + 1) ^ kg) << 2)) =
                make_float4(ev[kk][4], ev[kk][5], ev[kk][6], ev[kk][7]);
        }
        __syncthreads();

        // ---- GEMM2: O += S . V  (8 rows x 4 cols; V read as dup-pairs) ----
        #pragma unroll 4
        for (int x = 0; x < 16; x++) {
            const float *sa = sm + KS_OFF + x * 512 + (((2 * rg)     ^ x) << 2);
            const float *sb = sm + KS_OFF + x * 512 + (((2 * rg + 1) ^ x) << 2);
            const int m4 = (x & 3) * 4;
            #pragma unroll
            for (int kk = 0; kk < 4; kk++) {
                ulonglong2 sA = *(const ulonglong2 *)(sa + kk * 128);
                ulonglong2 sB = *(const ulonglong2 *)(sb + kk * 128);
                const float *vb = sm + SV_OFF + (x * 4 + kk) * 128 +
                                  ((kg ^ (m4 + kk)) << 1);
                ull v0 = *(const ull *)(vb);
                ull v1 = *(const ull *)(vb + 32);
                ull v2 = *(const ull *)(vb + 64);
                ull v3 = *(const ull *)(vb + 96);
                fma2(accO[0],  sA.x, v0); fma2(accO[1],  sA.y, v0);
                fma2(accO[2],  sB.x, v0); fma2(accO[3],  sB.y, v0);
                fma2(accO[4],  sA.x, v1); fma2(accO[5],  sA.y, v1);
                fma2(accO[6],  sB.x, v1); fma2(accO[7],  sB.y, v1);
                fma2(accO[8],  sA.x, v2); fma2(accO[9],  sA.y, v2);
                fma2(accO[10], sB.x, v2); fma2(accO[11], sB.y, v2);
                fma2(accO[12], sA.x, v3); fma2(accO[13], sA.y, v3);
                fma2(accO[14], sB.x, v3); fma2(accO[15], sB.y, v3);
            }
        }
        __syncthreads();   // all GEMM2 reads of S done before next chunk's stage
    }

    // ---- row sums: butterfly over the 16 kg lanes (half-warp) ----
    float rec[8];
    #pragma unroll
    for (int rr = 0; rr < 8; rr++) {
        float v = msum[rr];
        v += __shfl_xor_sync(0xffffffffu, v, 1);
        v += __shfl_xor_sync(0xffffffffu, v, 2);
        v += __shfl_xor_sync(0xffffffffu, v, 4);
        v += __shfl_xor_sync(0xffffffffu, v, 8);
        rec[rr] = 1.0f / v;
    }

    // ---- O write: 8 rows x this thread's 4 E-cols ----
    #pragma unroll
    for (int rp = 0; rp < 4; rp++) {
        float o0[4], o1[4];
        #pragma unroll
        for (int cc = 0; cc < 4; cc++)
            unpack2(accO[cc * 4 + rp], o0[cc], o1[cc]);
        const int r0 = blk * BS + hf * 128 + rg * 8 + 2 * rp;
        float rc0 = rec[2 * rp], rc1 = rec[2 * rp + 1];
        __stcs((float4 *)(out + ((size_t)(b * LL + r0) * HH + h) * EE + kg * 4),
               make_float4(o0[0] * rc0, o0[1] * rc0, o0[2] * rc0, o0[3] * rc0));
        __stcs((float4 *)(out + ((size_t)(b * LL + r0 + 1) * HH + h) * EE + kg * 4),
               make_float4(o1[0] * rc1, o1[1] * rc1, o1[2] * rc1, o1[3] * rc1));
    }

    // ---- normalize attn diag rows in place (L2-hot) ----
    #pragma unroll
    for (int c = 0; c < 4; c++) {
        #pragma unroll
        for (int rr = 0; rr < 8; rr++) {
            float4 *ap = (float4 *)(attnBase + (size_t)(rg * 8 + rr) * LL + c * 64 + kg * 4);
            float4 v = *ap;
            float rc = rec[rr];
            v.x *= rc; v.y *= rc; v.z *= rc; v.w *= rc;
            *ap = v;
        }
    }
}

extern "C" void kernel_launch(void *const *d_in, const int *in_sizes, int n_in,
                              void *d_out, int out_size) {
    const float *Q = (const float *)d_in[0];
    const float *K = (const float *)d_in[1];
    const float *V = (const float *)d_in[2];
    float *out = (float *)d_out;

    const int smem_bytes = SMEMF * (int)sizeof(float); // 98304
    cudaFuncSetAttribute(sparse_attn_kernel,
                         cudaFuncAttributeMaxDynamicSharedMemorySize, smem_bytes);
    sparse_attn_kernel<<<BB * HH * NB * 2, 256, smem_bytes>>>(Q, K, V, out);
}

// round 11
// speedup vs baseline: 1.0260x; 1.0260x over previous
#include <cuda_runtime.h>
#include <cstdint>
#include <cstddef>

#define BB 2
#define LL 2048
#define HH 16
#define EE 64
#define BS 256
#define NB (LL / BS)                  // 8 blocks
#define OUT_ELEMS (BB * LL * HH * EE) // output tensor precedes attn in d_out

// smem layout (floats)
#define QT_OFF 0                      // Q^T: 64 e x 128 rows (quad-swizzled)       8192 f
#define KD_OFF 8192                   // K chunk, duplicated pairs: 64 e x 128      8192 f
#define SS_OFF 16384                  // S chunk: 64 keys x 128 rows (swizzled)     8192 f
#define SV_OFF 24576                  // V chunk: 64 keys x 64 cols (row-major)     4096 f
#define SMEMF  28672                  // 114688 bytes -> 2 CTAs/SM (229376 <= 228KB cap)

typedef unsigned long long ull;

__device__ __forceinline__ ull pack2(float lo, float hi) {
    ull r;
    asm("mov.b64 %0, {%1, %2};" : "=l"(r) : "f"(lo), "f"(hi));
    return r;
}
__device__ __forceinline__ void unpack2(ull p, float &lo, float &hi) {
    asm("mov.b64 {%0, %1}, %2;" : "=f"(lo), "=f"(hi) : "l"(p));
}
__device__ __forceinline__ void fma2(ull &d, ull a, ull b) {
    asm("fma.rn.f32x2 %0, %1, %2, %0;" : "+l"(d) : "l"(a), "l"(b));
}

extern __shared__ float sm[];

__global__ void __launch_bounds__(256, 2)
sparse_attn_kernel(const float *__restrict__ Q,
                   const float *__restrict__ K,
                   const float *__restrict__ V,
                   float *__restrict__ out) {
    const int tid = threadIdx.x;
    const int bid = blockIdx.x;
    const int hf  = bid & 1;          // which 128-row half of the block
    const int blk = (bid >> 1) & 7;
    const int h   = (bid >> 4) & 15;
    const int b   = bid >> 8;

    const int kg = tid & 15;   // key/col group (4 wide)
    const int rg = tid >> 4;   // row group: rows rg*8 .. rg*8+7 (local, 0..127)

    const float *Qrow = Q + ((size_t)(b * LL + blk * BS + hf * 128) * HH + h) * EE;
    const float *Krow = K + ((size_t)(b * LL + blk * BS) * HH + h) * EE;
    const float *Vrow = V + ((size_t)(b * LL + blk * BS) * HH + h) * EE;

    float *attnBase = out + (size_t)OUT_ELEMS + (size_t)(b * HH + h) * LL * LL +
                      (size_t)(blk * BS + hf * 128) * LL + (size_t)(blk * BS);
    float *attnCta  = out + (size_t)OUT_ELEMS + (size_t)(b * HH + h) * LL * LL +
                      (size_t)(blk * BS + hf * 128) * LL;
    const int blk64 = blk * 64;

    // ---- stage Q transposed with quad-swizzle: [e][quad ^ (e>>2)] ----
    #pragma unroll
    for (int i = 0; i < 8; i++) {
        int idx = i * 256 + tid;        // 2048 float4
        int r   = idx >> 4;
        int c4  = idx & 15;
        float4 f = *(const float4 *)(Qrow + r * 1024 + c4 * 4);
        const int q  = r >> 2;
        const int rl = r & 3;
        sm[QT_OFF + (c4 * 4 + 0) * 128 + ((q ^ c4) << 2) + rl] = f.x;
        sm[QT_OFF + (c4 * 4 + 1) * 128 + ((q ^ c4) << 2) + rl] = f.y;
        sm[QT_OFF + (c4 * 4 + 2) * 128 + ((q ^ c4) << 2) + rl] = f.z;
        sm[QT_OFF + (c4 * 4 + 3) * 128 + ((q ^ c4) << 2) + rl] = f.w;
    }

    ull accO[16];                       // accO[cc*4+rp]
    #pragma unroll
    for (int i = 0; i < 16; i++) accO[i] = 0ULL;
    float msum[8];
    #pragma unroll
    for (int i = 0; i < 8; i++) msum[i] = 0.f;

    for (int c = 0; c < 4; c++) {
        // ---- stage K chunk DUPLICATED pair-contiguous + V chunk row-major ----
        // K[key=4g+m][e] dup -> KD + e*128 + (m>>1)*64 + ((g ^ (e&15))<<2) + (m&1)*2
        #pragma unroll
        for (int i = 0; i < 4; i++) {
            int idx = i * 256 + tid;    // 1024 float4 per tensor
            int key = idx >> 4;
            int c4  = idx & 15;
            float4 f = *(const float4 *)(Krow + (size_t)(c * 64 + key) * 1024 + c4 * 4);
            const int g  = key >> 2;
            const int hb = ((key & 3) >> 1) * 64 + (key & 1) * 2;
            float fv[4] = {f.x, f.y, f.z, f.w};
            #pragma unroll
            for (int j = 0; j < 4; j++) {
                const int e = c4 * 4 + j;
                *(ull *)(sm + KD_OFF + e * 128 + hb + ((g ^ (e & 15)) << 2)) =
                    pack2(fv[j], fv[j]);
            }
            float4 gg = *(const float4 *)(Vrow + (size_t)(c * 64 + key) * 1024 + c4 * 4);
            *(float4 *)(sm + SV_OFF + key * 64 + c4 * 4) = gg;
        }
        // ---- interleaved zero-fill of this CTA's off-diag rows ----
        {
            #pragma unroll
            for (int rr = 0; rr < 2; rr++) {
                float *zp = attnCta + (size_t)(rg + 32 * c + 16 * rr) * LL;
                #pragma unroll 7
                for (int j = 0; j < 28; j++) {
                    int c4 = j * 16 + kg;
                    c4 = (c4 >= blk64) ? c4 + 64 : c4;
                    __stcs((float4 *)(zp + c4 * 4),
                           make_float4(0.f, 0.f, 0.f, 0.f));
                }
            }
        }
        __syncthreads();

        // ---- GEMM1: S = Q . K^T  (8 rows x 4 keys; K read as dup'd LDS.128) ----
        ull acc[16];
        #pragma unroll
        for (int i = 0; i < 16; i++) acc[i] = 0ULL;
        #pragma unroll 4
        for (int x = 0; x < 16; x++) {
            const float *qa = sm + QT_OFF + x * 512 + (((2 * rg)     ^ x) << 2);
            const float *qb = sm + QT_OFF + x * 512 + (((2 * rg + 1) ^ x) << 2);
            #pragma unroll
            for (int ee = 0; ee < 4; ee++) {
                ulonglong2 qA = *(const ulonglong2 *)(qa + ee * 128);
                ulonglong2 qB = *(const ulonglong2 *)(qb + ee * 128);
                const int e4 = (x & 3) * 4 + ee;
                const float *kb = sm + KD_OFF + (x * 4 + ee) * 128 + ((kg ^ e4) << 2);
                ulonglong2 kd0 = *(const ulonglong2 *)(kb);
                ulonglong2 kd1 = *(const ulonglong2 *)(kb + 64);
                fma2(acc[0],  qA.x, kd0.x); fma2(acc[1],  qA.y, kd0.x);
                fma2(acc[2],  qB.x, kd0.x); fma2(acc[3],  qB.y, kd0.x);
                fma2(acc[4],  qA.x, kd0.y); fma2(acc[5],  qA.y, kd0.y);
                fma2(acc[6],  qB.x, kd0.y); fma2(acc[7],  qB.y, kd0.y);
                fma2(acc[8],  qA.x, kd1.x); fma2(acc[9],  qA.y, kd1.x);
                fma2(acc[10], qB.x, kd1.x); fma2(acc[11], qB.y, kd1.x);
                fma2(acc[12], qA.x, kd1.y); fma2(acc[13], qA.y, kd1.y);
                fma2(acc[14], qB.x, kd1.y); fma2(acc[15], qB.y, kd1.y);
            }
        }
        // ---- epilogue: exp, row partial sums, attn STG, S -> smem (swizzled) ----
        {
            float ev[4][8];
            #pragma unroll
            for (int kk = 0; kk < 4; kk++)
                #pragma unroll
                for (int rp = 0; rp < 4; rp++)
                    unpack2(acc[kk * 4 + rp], ev[kk][2 * rp], ev[kk][2 * rp + 1]);
            #pragma unroll
            for (int kk = 0; kk < 4; kk++)
                #pragma unroll
                for (int rr = 0; rr < 8; rr++)
                    ev[kk][rr] = __expf(ev[kk][rr]);   // no-max softmax: |s| bounded
            #pragma unroll
            for (int rr = 0; rr < 8; rr++)
                msum[rr] += (ev[0][rr] + ev[1][rr]) + (ev[2][rr] + ev[3][rr]);

            float *arow = attnBase + (size_t)(rg * 8) * LL + c * 64 + kg * 4;
            #pragma unroll
            for (int rr = 0; rr < 8; rr++)
                *(float4 *)(arow + (size_t)rr * LL) =
                    make_float4(ev[0][rr], ev[1][rr], ev[2][rr], ev[3][rr]);

            #pragma unroll
            for (int kk = 0; kk < 4; kk++) {
                const int key = kg * 4 + kk;
                float *spb = sm + SS_OFF + key * 128;
                *(float4 *)(spb + (((2 * rg)     ^ kg) << 2)) =
                    make_float4(ev[kk][0], ev[kk][1], ev[kk][2], ev[kk][3]);
                *(float4 *)(spb + (((2 * rg + 1) ^ kg) << 2)) =
                    make_float4(ev[kk][4], ev[kk][5], ev[kk][6], ev[kk][7]);
            }
        }
        __syncthreads();

        // ---- GEMM2: O += S . V  (thread tile 8 rows x 4 cols) ----
        #pragma unroll 4
        for (int x = 0; x < 16; x++) {
            const float *sa = sm + SS_OFF + x * 512 + (((2 * rg)     ^ x) << 2);
            const float *sb = sm + SS_OFF + x * 512 + (((2 * rg + 1) ^ x) << 2);
            const float *vb = sm + SV_OFF + x * 256 + kg * 4;
            #pragma unroll
            for (int kk = 0; kk < 4; kk++) {
                ulonglong2 sA = *(const ulonglong2 *)(sa + kk * 128);
                ulonglong2 sB = *(const ulonglong2 *)(sb + kk * 128);
                float4 vv = *(const float4 *)(vb + kk * 64);
                ull v0 = pack2(vv.x, vv.x);
                ull v1 = pack2(vv.y, vv.y);
                ull v2 = pack2(vv.z, vv.z);
                ull v3 = pack2(vv.w, vv.w);
                fma2(accO[0],  sA.x, v0); fma2(accO[1],  sA.y, v0);
                fma2(accO[2],  sB.x, v0); fma2(accO[3],  sB.y, v0);
                fma2(accO[4],  sA.x, v1); fma2(accO[5],  sA.y, v1);
                fma2(accO[6],  sB.x, v1); fma2(accO[7],  sB.y, v1);
                fma2(accO[8],  sA.x, v2); fma2(accO[9],  sA.y, v2);
                fma2(accO[10], sB.x, v2); fma2(accO[11], sB.y, v2);
                fma2(accO[12], sA.x, v3); fma2(accO[13], sA.y, v3);
                fma2(accO[14], sB.x, v3); fma2(accO[15], sB.y, v3);
            }
        }
        __syncthreads();
    }

    // ---- row sums: butterfly over the 16 kg lanes (half-warp) ----
    float rec[8];
    #pragma unroll
    for (int rr = 0; rr < 8; rr++) {
        float v = msum[rr];
        v += __shfl_xor_sync(0xffffffffu, v, 1);
        v += __shfl_xor_sync(0xffffffffu, v, 2);
        v += __shfl_xor_sync(0xffffffffu, v, 4);
        v += __shfl_xor_sync(0xffffffffu, v, 8);
        rec[rr] = 1.0f / v;
    }

    // ---- O write: 8 rows x this thread's 4 E-cols ----
    #pragma unroll
    for (int rp = 0; rp < 4; rp++) {
        float o0[4], o1[4];
        #pragma unroll
        for (int cc = 0; cc < 4; cc++)
            unpack2(accO[cc * 4 + rp], o0[cc], o1[cc]);
        const int r0 = blk * BS + hf * 128 + rg * 8 + 2 * rp;
        float rc0 = rec[2 * rp], rc1 = rec[2 * rp + 1];
        __stcs((float4 *)(out + ((size_t)(b * LL + r0) * HH + h) * EE + kg * 4),
               make_float4(o0[0] * rc0, o0[1] * rc0, o0[2] * rc0, o0[3] * rc0));
        __stcs((float4 *)(out + ((size_t)(b * LL + r0 + 1) * HH + h) * EE + kg * 4),
               make_float4(o1[0] * rc1, o1[1] * rc1, o1[2] * rc1, o1[3] * rc1));
    }

    // ---- normalize attn diag rows in place (L2-hot) ----
    #pragma unroll
    for (int c = 0; c < 4; c++) {
        #pragma unroll
        for (int rr = 0; rr < 8; rr++) {
            float4 *ap = (float4 *)(attnBase + (size_t)(rg * 8 + rr) * LL + c * 64 + kg * 4);
            float4 v = *ap;
            float rc = rec[rr];
            v.x *= rc; v.y *= rc; v.z *= rc; v.w *= rc;
            *ap = v;
        }
    }
}

extern "C" void kernel_launch(void *const *d_in, const int *in_sizes, int n_in,
                              void *d_out, int out_size) {
    const float *Q = (const float *)d_in[0];
    const float *K = (const float *)d_in[1];
    const float *V = (const float *)d_in[2];
    float *out = (float *)d_out;

    const int smem_bytes = SMEMF * (int)sizeof(float); // 114688
    cudaFuncSetAttribute(sparse_attn_kernel,
                         cudaFuncAttributeMaxDynamicSharedMemorySize, smem_bytes);
    sparse_attn_kernel<<<BB * HH * NB * 2, 256, smem_bytes>>>(Q, K, V, out);
}

// round 12
// speedup vs baseline: 1.1718x; 1.1421x over previous
#include <cuda_runtime.h>
#include <cstdint>
#include <cstddef>

#define BB 2
#define LL 2048
#define HH 16
#define EE 64
#define BS 256
#define NB (LL / BS)                  // 8 blocks
#define OUT_ELEMS (BB * LL * HH * EE) // output tensor precedes attn in d_out

// smem layout (floats) — XOR-swizzled, no padding
#define QT_OFF 0                      // Q^T: 64 e x 128 rows (32 quads, swizzled)
#define KT_OFF 8192                   // K^T chunk: 64 e x 64 keys (16 quads, swizzled)
#define SS_OFF 12288                  // S chunk: 64 keys x 128 rows (32 quads, swizzled)
#define SV_OFF 20480                  // V chunk: 64 keys x 64 cols (row-major)
#define SMEMF  24576                  // 98304 bytes -> 2 CTAs/SM

typedef unsigned long long ull;

__device__ __forceinline__ ull pack2(float lo, float hi) {
    ull r;
    asm("mov.b64 %0, {%1, %2};" : "=l"(r) : "f"(lo), "f"(hi));
    return r;
}
__device__ __forceinline__ void unpack2(ull p, float &lo, float &hi) {
    asm("mov.b64 {%0, %1}, %2;" : "=f"(lo), "=f"(hi) : "l"(p));
}
__device__ __forceinline__ void fma2(ull &d, ull a, ull b) {
    asm("fma.rn.f32x2 %0, %1, %2, %0;" : "+l"(d) : "l"(a), "l"(b));
}

extern __shared__ float sm[];

__global__ void __launch_bounds__(256, 2)
sparse_attn_kernel(const float *__restrict__ Q,
                   const float *__restrict__ K,
                   const float *__restrict__ V,
                   float *__restrict__ out) {
    const int tid = threadIdx.x;
    const int bid = blockIdx.x;
    const int hf  = bid & 1;          // which 128-row half of the block
    const int blk = (bid >> 1) & 7;
    const int h   = (bid >> 4) & 15;
    const int b   = bid >> 8;

    const int kg = tid & 15;   // key/col group (4 wide)
    const int rg = tid >> 4;   // row group: rows rg*8 .. rg*8+7 (local, 0..127)

    const float *Qrow = Q + ((size_t)(b * LL + blk * BS + hf * 128) * HH + h) * EE;
    const float *Krow = K + ((size_t)(b * LL + blk * BS) * HH + h) * EE;
    const float *Vrow = V + ((size_t)(b * LL + blk * BS) * HH + h) * EE;

    float *attnBase = out + (size_t)OUT_ELEMS + (size_t)(b * HH + h) * LL * LL +
                      (size_t)(blk * BS + hf * 128) * LL + (size_t)(blk * BS);
    float *attnCta  = out + (size_t)OUT_ELEMS + (size_t)(b * HH + h) * LL * LL +
                      (size_t)(blk * BS + hf * 128) * LL;
    const int blk64 = blk * 64;

    // ---- stage Q transposed with quad-swizzle: [e][quad ^ (e>>2)] ----
    #pragma unroll
    for (int i = 0; i < 8; i++) {
        int idx = i * 256 + tid;        // 2048 float4
        int r   = idx >> 4;
        int c4  = idx & 15;
        float4 f = *(const float4 *)(Qrow + r * 1024 + c4 * 4);
        const int q  = r >> 2;
        const int rl = r & 3;
        sm[QT_OFF + (c4 * 4 + 0) * 128 + ((q ^ c4) << 2) + rl] = f.x;
        sm[QT_OFF + (c4 * 4 + 1) * 128 + ((q ^ c4) << 2) + rl] = f.y;
        sm[QT_OFF + (c4 * 4 + 2) * 128 + ((q ^ c4) << 2) + rl] = f.z;
        sm[QT_OFF + (c4 * 4 + 3) * 128 + ((q ^ c4) << 2) + rl] = f.w;
    }

    ull accO[16];                       // accO[cc*4+rp]
    #pragma unroll
    for (int i = 0; i < 16; i++) accO[i] = 0ULL;
    float msum[8];
    #pragma unroll
    for (int i = 0; i < 8; i++) msum[i] = 0.f;

    for (int c = 0; c < 4; c++) {
        // ---- stage K^T chunk (swizzled) and V chunk (row-major) ----
        #pragma unroll
        for (int i = 0; i < 4; i++) {
            int idx = i * 256 + tid;    // 1024 float4
            int key = idx >> 4;
            int c4  = idx & 15;
            float4 f = *(const float4 *)(Krow + (size_t)(c * 64 + key) * 1024 + c4 * 4);
            const int q  = key >> 2;
            const int kl = key & 3;
            sm[KT_OFF + (c4 * 4 + 0) * 64 + ((q ^ c4) << 2) + kl] = f.x;
            sm[KT_OFF + (c4 * 4 + 1) * 64 + ((q ^ c4) << 2) + kl] = f.y;
            sm[KT_OFF + (c4 * 4 + 2) * 64 + ((q ^ c4) << 2) + kl] = f.z;
            sm[KT_OFF + (c4 * 4 + 3) * 64 + ((q ^ c4) << 2) + kl] = f.w;
            float4 g = *(const float4 *)(Vrow + (size_t)(c * 64 + key) * 1024 + c4 * 4);
            *(float4 *)(sm + SV_OFF + key * 64 + c4 * 4) = g;
        }
        // ---- interleaved zero-fill of this CTA's off-diag rows ----
        {
            #pragma unroll
            for (int rr = 0; rr < 2; rr++) {
                float *zp = attnCta + (size_t)(rg + 32 * c + 16 * rr) * LL;
                #pragma unroll 7
                for (int j = 0; j < 28; j++) {
                    int c4 = j * 16 + kg;
                    c4 = (c4 >= blk64) ? c4 + 64 : c4;
                    __stcs((float4 *)(zp + c4 * 4),
                           make_float4(0.f, 0.f, 0.f, 0.f));
                }
            }
        }
        __syncthreads();   // KT/SV staged (CTA-wide), prev GEMM2 done

        // ============ barrier-free per-warp region begins ============

        // ---- GEMM1: S = Q . K^T  (thread tile 8 rows x 4 keys) ----
        ull acc[16];
        #pragma unroll
        for (int i = 0; i < 16; i++) acc[i] = 0ULL;
        #pragma unroll 4
        for (int x = 0; x < 16; x++) {
            const float *qa = sm + QT_OFF + x * 512 + (((2 * rg)     ^ x) << 2);
            const float *qb = sm + QT_OFF + x * 512 + (((2 * rg + 1) ^ x) << 2);
            const float *kb = sm + KT_OFF + x * 256 + ((kg ^ x) << 2);
            #pragma unroll
            for (int ee = 0; ee < 4; ee++) {
                ulonglong2 qA = *(const ulonglong2 *)(qa + ee * 128);
                ulonglong2 qB = *(const ulonglong2 *)(qb + ee * 128);
                float4 kv = *(const float4 *)(kb + ee * 64);
                ull k0 = pack2(kv.x, kv.x);
                ull k1 = pack2(kv.y, kv.y);
                ull k2 = pack2(kv.z, kv.z);
                ull k3 = pack2(kv.w, kv.w);
                fma2(acc[0],  qA.x, k0); fma2(acc[1],  qA.y, k0);
                fma2(acc[2],  qB.x, k0); fma2(acc[3],  qB.y, k0);
                fma2(acc[4],  qA.x, k1); fma2(acc[5],  qA.y, k1);
                fma2(acc[6],  qB.x, k1); fma2(acc[7],  qB.y, k1);
                fma2(acc[8],  qA.x, k2); fma2(acc[9],  qA.y, k2);
                fma2(acc[10], qB.x, k2); fma2(acc[11], qB.y, k2);
                fma2(acc[12], qA.x, k3); fma2(acc[13], qA.y, k3);
                fma2(acc[14], qB.x, k3); fma2(acc[15], qB.y, k3);
            }
        }
        // ---- epilogue: exp, row partial sums, S -> smem, attn STG ----
        {
            float ev[4][8];
            #pragma unroll
            for (int kk = 0; kk < 4; kk++)
                #pragma unroll
                for (int rp = 0; rp < 4; rp++)
                    unpack2(acc[kk * 4 + rp], ev[kk][2 * rp], ev[kk][2 * rp + 1]);
            #pragma unroll
            for (int kk = 0; kk < 4; kk++)
                #pragma unroll
                for (int rr = 0; rr < 8; rr++)
                    ev[kk][rr] = __expf(ev[kk][rr]);   // no-max softmax: |s| bounded
            #pragma unroll
            for (int rr = 0; rr < 8; rr++)
                msum[rr] += (ev[0][rr] + ev[1][rr]) + (ev[2][rr] + ev[3][rr]);

            // S-store first so GEMM2 can start right after syncwarp
            #pragma unroll
            for (int kk = 0; kk < 4; kk++) {
                const int key = kg * 4 + kk;
                float *spb = sm + SS_OFF + key * 128;
                *(float4 *)(spb + (((2 * rg)     ^ kg) << 2)) =
                    make_float4(ev[kk][0], ev[kk][1], ev[kk][2], ev[kk][3]);
                *(float4 *)(spb + (((2 * rg + 1) ^ kg) << 2)) =
                    make_float4(ev[kk][4], ev[kk][5], ev[kk][6], ev[kk][7]);
            }

            float *arow = attnBase + (size_t)(rg * 8) * LL + c * 64 + kg * 4;
            #pragma unroll
            for (int rr = 0; rr < 8; rr++)
                *(float4 *)(arow + (size_t)rr * LL) =
                    make_float4(ev[0][rr], ev[1][rr], ev[2][rr], ev[3][rr]);
        }
        // S producer->consumer edge is within-warp: lane (rg,kg) writes row-quads
        // 2rg/2rg+1; readers of those quads are lanes with the same rg, i.e. the
        // same warp (warp = rg>>1). Warp-level sync suffices — no CTA barrier.
        __syncwarp(0xffffffffu);

        // ---- GEMM2: O += S . V  (thread tile 8 rows x 4 cols) ----
        #pragma unroll 4
        for (int x = 0; x < 16; x++) {
            const float *sa = sm + SS_OFF + x * 512 + (((2 * rg)     ^ x) << 2);
            const float *sb = sm + SS_OFF + x * 512 + (((2 * rg + 1) ^ x) << 2);
            const float *vb = sm + SV_OFF + x * 256 + kg * 4;
            #pragma unroll
            for (int kk = 0; kk < 4; kk++) {
                ulonglong2 sA = *(const ulonglong2 *)(sa + kk * 128);
                ulonglong2 sB = *(const ulonglong2 *)(sb + kk * 128);
                float4 vv = *(const float4 *)(vb + kk * 64);
                ull v0 = pack2(vv.x, vv.x);
                ull v1 = pack2(vv.y, vv.y);
                ull v2 = pack2(vv.z, vv.z);
                ull v3 = pack2(vv.w, vv.w);
                fma2(accO[0],  sA.x, v0); fma2(accO[1],  sA.y, v0);
                fma2(accO[2],  sB.x, v0); fma2(accO[3],  sB.y, v0);
                fma2(accO[4],  sA.x, v1); fma2(accO[5],  sA.y, v1);
                fma2(accO[6],  sB.x, v1); fma2(accO[7],  sB.y, v1);
                fma2(accO[8],  sA.x, v2); fma2(accO[9],  sA.y, v2);
                fma2(accO[10], sB.x, v2); fma2(accO[11], sB.y, v2);
                fma2(accO[12], sA.x, v3); fma2(accO[13], sA.y, v3);
                fma2(accO[14], sB.x, v3); fma2(accO[15], sB.y, v3);
            }
        }
        __syncthreads();   // all warps done reading KT/SV before next staging
    }

    // ---- row sums: butterfly over the 16 kg lanes (half-warp) ----
    float rec[8];
    #pragma unroll
    for (int rr = 0; rr < 8; rr++) {
        float v = msum[rr];
        v += __shfl_xor_sync(0xffffffffu, v, 1);
        v += __shfl_xor_sync(0xffffffffu, v, 2);
        v += __shfl_xor_sync(0xffffffffu, v, 4);
        v += __shfl_xor_sync(0xffffffffu, v, 8);
        rec[rr] = 1.0f / v;
    }

    // ---- O write: 8 rows x this thread's 4 E-cols ----
    #pragma unroll
    for (int rp = 0; rp < 4; rp++) {
        float o0[4], o1[4];
        #pragma unroll
        for (int cc = 0; cc < 4; cc++)
            unpack2(accO[cc * 4 + rp], o0[cc], o1[cc]);
        const int r0 = blk * BS + hf * 128 + rg * 8 + 2 * rp;
        float rc0 = rec[2 * rp], rc1 = rec[2 * rp + 1];
        __stcs((float4 *)(out + ((size_t)(b * LL + r0) * HH + h) * EE + kg * 4),
               make_float4(o0[0] * rc0, o0[1] * rc0, o0[2] * rc0, o0[3] * rc0));
        __stcs((float4 *)(out + ((size_t)(b * LL + r0 + 1) * HH + h) * EE + kg * 4),
               make_float4(o1[0] * rc1, o1[1] * rc1, o1[2] * rc1, o1[3] * rc1));
    }

    // ---- normalize attn diag rows in place (L2-hot) ----
    #pragma unroll
    for (int c = 0; c < 4; c++) {
        #pragma unroll
        for (int rr = 0; rr < 8; rr++) {
            float4 *ap = (float4 *)(attnBase + (size_t)(rg * 8 + rr) * LL + c * 64 + kg * 4);
            float4 v = *ap;
            float rc = rec[rr];
            v.x *= rc; v.y *= rc; v.z *= rc; v.w *= rc;
            *ap = v;
        }
    }
}

extern "C" void kernel_launch(void *const *d_in, const int *in_sizes, int n_in,
                              void *d_out, int out_size) {
    const float *Q = (const float *)d_in[0];
    const float *K = (const float *)d_in[1];
    const float *V = (const float *)d_in[2];
    float *out = (float *)d_out;

    const int smem_bytes = SMEMF * (int)sizeof(float); // 98304
    cudaFuncSetAttribute(sparse_attn_kernel,
                         cudaFuncAttributeMaxDynamicSharedMemorySize, smem_bytes);
    sparse_attn_kernel<<<BB * HH * NB * 2, 256, smem_bytes>>>(Q, K, V, out);
}

// round 13
// speedup vs baseline: 1.2281x; 1.0480x over previous
#include <cuda_runtime.h>
#include <cstdint>
#include <cstddef>

#define BB 2
#define LL 2048
#define HH 16
#define EE 64
#define BS 256
#define NB (LL / BS)                  // 8 blocks of 256
#define OUT_ELEMS (BB * LL * HH * EE) // output tensor precedes attn in d_out

// smem layout (floats) — XOR-swizzled, no padding. 64-row CTA.
#define QT_OFF 0                      // Q^T: 64 e x 64 rows (16 quads, swizzled)
#define KT_OFF 4096                   // K^T chunk: 64 e x 64 keys (swizzled)
#define SS_OFF 8192                   // S chunk: 64 keys x 64 rows (swizzled)
#define SV_OFF 12288                  // V chunk: 64 keys x 64 cols (row-major)
#define SMEMF  16384                  // 65536 bytes -> 3 CTAs/SM

typedef unsigned long long ull;

__device__ __forceinline__ ull pack2(float lo, float hi) {
    ull r;
    asm("mov.b64 %0, {%1, %2};" : "=l"(r) : "f"(lo), "f"(hi));
    return r;
}
__device__ __forceinline__ void unpack2(ull p, float &lo, float &hi) {
    asm("mov.b64 {%0, %1}, %2;" : "=f"(lo), "=f"(hi) : "l"(p));
}
__device__ __forceinline__ void fma2(ull &d, ull a, ull b) {
    asm("fma.rn.f32x2 %0, %1, %2, %0;" : "+l"(d) : "l"(a), "l"(b));
}

extern __shared__ float sm[];

__global__ void __launch_bounds__(256, 3)
sparse_attn_kernel(const float *__restrict__ Q,
                   const float *__restrict__ K,
                   const float *__restrict__ V,
                   float *__restrict__ out) {
    const int tid = threadIdx.x;
    const int bid = blockIdx.x;
    const int qf  = bid & 3;          // which 64-row quarter of the 256-block
    const int blk = (bid >> 2) & 7;
    const int h   = (bid >> 5) & 15;
    const int b   = bid >> 9;

    const int kg = tid & 31;   // key/col group (2 wide) — warp spans all kg
    const int rg = tid >> 5;   // row group: rows rg*8 .. rg*8+7 (local, 0..63)

    const float *Qrow = Q + ((size_t)(b * LL + blk * BS + qf * 64) * HH + h) * EE;
    const float *Krow = K + ((size_t)(b * LL + blk * BS) * HH + h) * EE;
    const float *Vrow = V + ((size_t)(b * LL + blk * BS) * HH + h) * EE;

    float *attnBase = out + (size_t)OUT_ELEMS + (size_t)(b * HH + h) * LL * LL +
                      (size_t)(blk * BS + qf * 64) * LL + (size_t)(blk * BS);
    float *attnCta  = out + (size_t)OUT_ELEMS + (size_t)(b * HH + h) * LL * LL +
                      (size_t)(blk * BS + qf * 64) * LL;
    const int blk64 = blk * 64;

    // ---- stage Q transposed with quad-swizzle: [e][rowquad ^ (e>>2)] ----
    #pragma unroll
    for (int i = 0; i < 4; i++) {
        int idx = i * 256 + tid;        // 1024 float4
        int r   = idx >> 4;             // 0..63
        int c4  = idx & 15;
        float4 f = *(const float4 *)(Qrow + r * 1024 + c4 * 4);
        const int q  = r >> 2;
        const int rl = r & 3;
        sm[QT_OFF + (c4 * 4 + 0) * 64 + ((q ^ c4) << 2) + rl] = f.x;
        sm[QT_OFF + (c4 * 4 + 1) * 64 + ((q ^ c4) << 2) + rl] = f.y;
        sm[QT_OFF + (c4 * 4 + 2) * 64 + ((q ^ c4) << 2) + rl] = f.z;
        sm[QT_OFF + (c4 * 4 + 3) * 64 + ((q ^ c4) << 2) + rl] = f.w;
    }

    ull accO[8];                        // accO[cc*4+rp]: col kg*2+cc, row-pair rp
    #pragma unroll
    for (int i = 0; i < 8; i++) accO[i] = 0ULL;
    float msum[8];
    #pragma unroll
    for (int i = 0; i < 8; i++) msum[i] = 0.f;

    for (int c = 0; c < 4; c++) {
        // ---- stage K^T chunk (swizzled) and V chunk (row-major) ----
        #pragma unroll
        for (int i = 0; i < 4; i++) {
            int idx = i * 256 + tid;    // 1024 float4 per tensor
            int key = idx >> 4;
            int c4  = idx & 15;
            float4 f = *(const float4 *)(Krow + (size_t)(c * 64 + key) * 1024 + c4 * 4);
            const int kq = key >> 2;
            const int kl = key & 3;
            sm[KT_OFF + (c4 * 4 + 0) * 64 + ((kq ^ c4) << 2) + kl] = f.x;
            sm[KT_OFF + (c4 * 4 + 1) * 64 + ((kq ^ c4) << 2) + kl] = f.y;
            sm[KT_OFF + (c4 * 4 + 2) * 64 + ((kq ^ c4) << 2) + kl] = f.z;
            sm[KT_OFF + (c4 * 4 + 3) * 64 + ((kq ^ c4) << 2) + kl] = f.w;
            float4 g = *(const float4 *)(Vrow + (size_t)(c * 64 + key) * 1024 + c4 * 4);
            *(float4 *)(sm + SV_OFF + key * 64 + c4 * 4) = g;
        }
        // ---- interleaved zero-fill: 16 rows x 448 f4 per chunk ----
        {
            const int cx = tid & 15;
            float *zp = attnCta + (size_t)(c * 16 + (tid >> 4)) * LL;
            #pragma unroll 7
            for (int j = 0; j < 28; j++) {
                int c4 = j * 16 + cx;
                c4 = (c4 >= blk64) ? c4 + 64 : c4;
                __stcs((float4 *)(zp + c4 * 4), make_float4(0.f, 0.f, 0.f, 0.f));
            }
        }
        __syncthreads();   // KT/SV staged; prev GEMM2 done

        // ---- GEMM1: S = Q . K^T  (thread tile 8 rows x 2 keys) ----
        ull acc[8];        // acc[k*4+rp]
        #pragma unroll
        for (int i = 0; i < 8; i++) acc[i] = 0ULL;
        #pragma unroll 4
        for (int x = 0; x < 16; x++) {
            const float *qa = sm + QT_OFF + x * 256 + (((2 * rg)     ^ x) << 2);
            const float *qb = sm + QT_OFF + x * 256 + (((2 * rg + 1) ^ x) << 2);
            const float *kb = sm + KT_OFF + x * 256 + (((kg >> 1) ^ x) << 2) + (kg & 1) * 2;
            #pragma unroll
            for (int ee = 0; ee < 4; ee++) {
                ulonglong2 qA = *(const ulonglong2 *)(qa + ee * 64); // rows 8rg..+3
                ulonglong2 qB = *(const ulonglong2 *)(qb + ee * 64); // rows 8rg+4..+7
                ull kd = *(const ull *)(kb + ee * 64);               // {K[2kg],K[2kg+1]}
                float k0, k1;
                unpack2(kd, k0, k1);
                ull kd0 = pack2(k0, k0);
                ull kd1 = pack2(k1, k1);
                fma2(acc[0], qA.x, kd0); fma2(acc[1], qA.y, kd0);
                fma2(acc[2], qB.x, kd0); fma2(acc[3], qB.y, kd0);
                fma2(acc[4], qA.x, kd1); fma2(acc[5], qA.y, kd1);
                fma2(acc[6], qB.x, kd1); fma2(acc[7], qB.y, kd1);
            }
        }
        // ---- epilogue: exp, row partial sums, S -> smem, attn STG ----
        {
            float ev[2][8];
            #pragma unroll
            for (int k = 0; k < 2; k++)
                #pragma unroll
                for (int rp = 0; rp < 4; rp++)
                    unpack2(acc[k * 4 + rp], ev[k][2 * rp], ev[k][2 * rp + 1]);
            #pragma unroll
            for (int k = 0; k < 2; k++)
                #pragma unroll
                for (int rr = 0; rr < 8; rr++)
                    ev[k][rr] = __expf(ev[k][rr]);   // no-max softmax: |s| bounded
            #pragma unroll
            for (int rr = 0; rr < 8; rr++)
                msum[rr] += ev[0][rr] + ev[1][rr];

            // S-store first so GEMM2 starts right after syncwarp
            #pragma unroll
            for (int k = 0; k < 2; k++) {
                const int key = kg * 2 + k;
                float *spb = sm + SS_OFF + key * 64;
                const int kq = key >> 2;
                *(float4 *)(spb + (((2 * rg)     ^ kq) << 2)) =
                    make_float4(ev[k][0], ev[k][1], ev[k][2], ev[k][3]);
                *(float4 *)(spb + (((2 * rg + 1) ^ kq) << 2)) =
                    make_float4(ev[k][4], ev[k][5], ev[k][6], ev[k][7]);
            }

            // attn diag: cols (2kg, 2kg+1) of 8 rows — 256B/warp coalesced STG.64
            float *arow = attnBase + (size_t)(rg * 8) * LL + c * 64 + kg * 2;
            #pragma unroll
            for (int rr = 0; rr < 8; rr++)
                *(ull *)(arow + (size_t)rr * LL) = pack2(ev[0][rr], ev[1][rr]);
        }
        // S rows-quads 2rg/2rg+1 are produced and consumed by warp rg only
        __syncwarp(0xffffffffu);

        // ---- GEMM2: O += S . V  (thread tile 8 rows x 2 cols) ----
        #pragma unroll 4
        for (int x = 0; x < 16; x++) {
            const float *sa = sm + SS_OFF + x * 256 + (((2 * rg)     ^ x) << 2);
            const float *sb = sm + SS_OFF + x * 256 + (((2 * rg + 1) ^ x) << 2);
            const float *vb = sm + SV_OFF + x * 256 + kg * 2;
            #pragma unroll
            for (int kk = 0; kk < 4; kk++) {
                ulonglong2 sA = *(const ulonglong2 *)(sa + kk * 64);
                ulonglong2 sB = *(const ulonglong2 *)(sb + kk * 64);
                ull vd = *(const ull *)(vb + kk * 64);   // {V[k][2kg], V[k][2kg+1]}
                float v0, v1;
                unpack2(vd, v0, v1);
                ull vd0 = pack2(v0, v0);
                ull vd1 = pack2(v1, v1);
                fma2(accO[0], sA.x, vd0); fma2(accO[1], sA.y, vd0);
                fma2(accO[2], sB.x, vd0); fma2(accO[3], sB.y, vd0);
                fma2(accO[4], sA.x, vd1); fma2(accO[5], sA.y, vd1);
                fma2(accO[6], sB.x, vd1); fma2(accO[7], sB.y, vd1);
            }
        }
        __syncthreads();   // all warps done reading KT/SV before next staging
    }

    // ---- row sums: butterfly over all 32 kg lanes ----
    float rec[8];
    #pragma unroll
    for (int rr = 0; rr < 8; rr++) {
        float v = msum[rr];
        v += __shfl_xor_sync(0xffffffffu, v, 1);
        v += __shfl_xor_sync(0xffffffffu, v, 2);
        v += __shfl_xor_sync(0xffffffffu, v, 4);
        v += __shfl_xor_sync(0xffffffffu, v, 8);
        v += __shfl_xor_sync(0xffffffffu, v, 16);
        rec[rr] = 1.0f / v;
    }

    // ---- O write: 8 rows x this thread's 2 E-cols (256B/warp per row) ----
    #pragma unroll
    for (int rp = 0; rp < 4; rp++) {
        float a0, a1, b0, b1;
        unpack2(accO[rp],     a0, a1);   // col0: rows 2rp, 2rp+1
        unpack2(accO[4 + rp], b0, b1);   // col1: rows 2rp, 2rp+1
        const int r0 = blk * BS + qf * 64 + rg * 8 + 2 * rp;
        float rc0 = rec[2 * rp], rc1 = rec[2 * rp + 1];
        __stcs((ull *)(out + ((size_t)(b * LL + r0) * HH + h) * EE + kg * 2),
               pack2(a0 * rc0, b0 * rc0));
        __stcs((ull *)(out + ((size_t)(b * LL + r0 + 1) * HH + h) * EE + kg * 2),
               pack2(a1 * rc1, b1 * rc1));
    }

    // ---- normalize attn diag rows in place (L2-hot) ----
    #pragma unroll
    for (int c = 0; c < 4; c++) {
        float *arow = attnBase + (size_t)(rg * 8) * LL + c * 64 + kg * 2;
        #pragma unroll
        for (int rr = 0; rr < 8; rr++) {
            ull p = *(ull *)(arow + (size_t)rr * LL);
            float lo, hi;
            unpack2(p, lo, hi);
            float rc = rec[rr];
            *(ull *)(arow + (size_t)rr * LL) = pack2(lo * rc, hi * rc);
        }
    }
}

extern "C" void kernel_launch(void *const *d_in, const int *in_sizes, int n_in,
                              void *d_out, int out_size) {
    const float *Q = (const float *)d_in[0];
    const float *K = (const float *)d_in[1];
    const float *V = (const float *)d_in[2];
    float *out = (float *)d_out;

    const int smem_bytes = SMEMF * (int)sizeof(float); // 65536
    cudaFuncSetAttribute(sparse_attn_kernel,
                         cudaFuncAttributeMaxDynamicSharedMemorySize, smem_bytes);
    sparse_attn_kernel<<<BB * HH * NB * 4, 256, smem_bytes>>>(Q, K, V, out);
}